// round 14
// baseline (speedup 1.0000x reference)
#include <cuda_runtime.h>

// Integrate-and-fire scan, TBN layout, pure HBM-streaming problem.
//   m_t = v_{t-1} + x_t ;  y_t = (m_t >= 1) ;  v_t = m_t - y_t
//
// R13: R7 structure (paired loads MLP=2, 4-wide back-to-back default-policy
// store bursts — the proven-best family) with the ONE never-tested axis:
// blockDim 256 -> 512. Each CTA now owns 8KB contiguous per timestep,
// 1024 CTAs total: fewer/larger per-CTA footprints in the LTS hash, better
// per-bank page locality. Everything else byte-identical to R7/R12.
//
// Calibration note (R12 vs R7, identical code): run-to-run variance is
// ~±2us kernel / ±2% DRAM. Solid findings: MLP>2 bad (R2/R5/R8),
// spill bad (R8), .cs bad (R2/R10), static-bn4 bad (R11).

#define T_STEPS 32

__device__ __forceinline__ void if_step(float4& v, float4 m, float4& s)
{
    m.x += v.x; m.y += v.y; m.z += v.z; m.w += v.w;
    s.x = (m.x >= 1.0f) ? 1.0f : 0.0f;
    s.y = (m.y >= 1.0f) ? 1.0f : 0.0f;
    s.z = (m.z >= 1.0f) ? 1.0f : 0.0f;
    s.w = (m.w >= 1.0f) ? 1.0f : 0.0f;
    v.x = m.x - s.x; v.y = m.y - s.y; v.z = m.z - s.z; v.w = m.w - s.w;
}

__global__ void __launch_bounds__(512) if_scan_kernel(
    const float4* __restrict__ x, float4* __restrict__ y, int bn4)
{
    const unsigned i = blockIdx.x * blockDim.x + threadIdx.x;

    const float4* xp = x + i;
    float4*       yp = y + i;

    float4 v = make_float4(0.f, 0.f, 0.f, 0.f);

    #pragma unroll
    for (int t = 0; t < T_STEPS; t += 4) {
        float4 s0, s1, s2, s3;

        // pair 1: load, consume
        {
            float4 m0 = xp[(unsigned)(t + 0) * (unsigned)bn4];
            float4 m1 = xp[(unsigned)(t + 1) * (unsigned)bn4];
            if_step(v, m0, s0);
            if_step(v, m1, s1);
        }
        // pair 2: load, consume (pair 1 loads already retired)
        {
            float4 m2 = xp[(unsigned)(t + 2) * (unsigned)bn4];
            float4 m3 = xp[(unsigned)(t + 3) * (unsigned)bn4];
            if_step(v, m2, s2);
            if_step(v, m3, s3);
        }

        // 4 stores back-to-back: 4KB contiguous write burst per warp
        yp[(unsigned)(t + 0) * (unsigned)bn4] = s0;
        yp[(unsigned)(t + 1) * (unsigned)bn4] = s1;
        yp[(unsigned)(t + 2) * (unsigned)bn4] = s2;
        yp[(unsigned)(t + 3) * (unsigned)bn4] = s3;
    }
}

extern "C" void kernel_launch(void* const* d_in, const int* in_sizes, int n_in,
                              void* d_out, int out_size)
{
    const float4* x = (const float4*)d_in[0];
    float4* y = (float4*)d_out;

    int total = in_sizes[0];           // T*B*N
    int bn = total / T_STEPS;          // B*N columns
    int bn4 = bn / 4;                  // 524288 float4 groups

    int threads = 512;
    int blocks = bn4 / threads;        // 1024, exact, no tail
    if_scan_kernel<<<blocks, threads>>>(x, y, bn4);
}

// round 15
// speedup vs baseline: 1.0758x; 1.0758x over previous
#include <cuda_runtime.h>

// Integrate-and-fire scan, TBN layout, pure HBM-streaming problem.
//   m_t = v_{t-1} + x_t ;  y_t = (m_t >= 1) ;  v_t = m_t - y_t
//
// FINAL (= R7, the empirical optimum over 12 experiments):
//   - one thread per float4 column group, T=32 scanned in registers
//   - 2048 CTAs x 256 threads, exact division, no guard, no tail
//   - loads strictly paired (max 2 outstanding; MLP>2 regressed 3x)
//   - 4 consecutive default-policy STG.128 per warp = 4KB write bursts
//     (burst curve: 1->78.3%, 2->80.0%, 4->81.7%, 8->80.5% DRAM)
//   - runtime bn4 (static-const offsets regressed: ALU const chains)
// Measured: 75.3us kernel, 81.7% DRAM, 6.47 TB/s — the 1:1 R/W mixed-stream
// HBM ceiling on GB300. Closed axes: .cs loads/stores, v8.f32, persistent
// grid, occ caps, static bn4, block=512.

#define T_STEPS 32

__device__ __forceinline__ void if_step(float4& v, float4 m, float4& s)
{
    m.x += v.x; m.y += v.y; m.z += v.z; m.w += v.w;
    s.x = (m.x >= 1.0f) ? 1.0f : 0.0f;
    s.y = (m.y >= 1.0f) ? 1.0f : 0.0f;
    s.z = (m.z >= 1.0f) ? 1.0f : 0.0f;
    s.w = (m.w >= 1.0f) ? 1.0f : 0.0f;
    v.x = m.x - s.x; v.y = m.y - s.y; v.z = m.z - s.z; v.w = m.w - s.w;
}

__global__ void __launch_bounds__(256) if_scan_kernel(
    const float4* __restrict__ x, float4* __restrict__ y, int bn4)
{
    const unsigned i = blockIdx.x * blockDim.x + threadIdx.x;

    const float4* xp = x + i;
    float4*       yp = y + i;

    float4 v = make_float4(0.f, 0.f, 0.f, 0.f);

    #pragma unroll
    for (int t = 0; t < T_STEPS; t += 4) {
        float4 s0, s1, s2, s3;

        // pair 1: load, consume
        {
            float4 m0 = xp[(unsigned)(t + 0) * (unsigned)bn4];
            float4 m1 = xp[(unsigned)(t + 1) * (unsigned)bn4];
            if_step(v, m0, s0);
            if_step(v, m1, s1);
        }
        // pair 2: load, consume (pair 1 loads already retired)
        {
            float4 m2 = xp[(unsigned)(t + 2) * (unsigned)bn4];
            float4 m3 = xp[(unsigned)(t + 3) * (unsigned)bn4];
            if_step(v, m2, s2);
            if_step(v, m3, s3);
        }

        // 4 stores back-to-back: 4KB contiguous write burst per warp
        yp[(unsigned)(t + 0) * (unsigned)bn4] = s0;
        yp[(unsigned)(t + 1) * (unsigned)bn4] = s1;
        yp[(unsigned)(t + 2) * (unsigned)bn4] = s2;
        yp[(unsigned)(t + 3) * (unsigned)bn4] = s3;
    }
}

extern "C" void kernel_launch(void* const* d_in, const int* in_sizes, int n_in,
                              void* d_out, int out_size)
{
    const float4* x = (const float4*)d_in[0];
    float4* y = (float4*)d_out;

    int total = in_sizes[0];           // T*B*N
    int bn = total / T_STEPS;          // B*N columns
    int bn4 = bn / 4;                  // 524288 float4 groups

    int threads = 256;
    int blocks = bn4 / threads;        // 2048, exact, no tail
    if_scan_kernel<<<blocks, threads>>>(x, y, bn4);
}